// round 6
// baseline (speedup 1.0000x reference)
#include <cuda_runtime.h>

#define BB 512
#define TT 200
#define MM 50
#define DKX 64
#define DVX 64
#define HHX 128
#define NSK 1000
#define NITEMS (BB*TT)

typedef unsigned long long u64;

// ---- packed f32x2 helpers ----
__device__ __forceinline__ u64 pk2(float lo, float hi) {
    u64 r; asm("mov.b64 %0,{%1,%2};" : "=l"(r) : "f"(lo), "f"(hi)); return r;
}
__device__ __forceinline__ u64 pkd(float x) {
    u64 r; asm("mov.b64 %0,{%1,%1};" : "=l"(r) : "f"(x)); return r;
}
__device__ __forceinline__ void up2(u64 v, float& lo, float& hi) {
    asm("mov.b64 {%0,%1},%2;" : "=f"(lo), "=f"(hi) : "l"(v));
}
__device__ __forceinline__ u64 ffma2(u64 a, u64 b, u64 c) {
    u64 d; asm("fma.rn.f32x2 %0,%1,%2,%3;" : "=l"(d) : "l"(a), "l"(b), "l"(c)); return d;
}

// ---- tables (device globals) ----
__device__ float tw[NSK*MM];          // softmax(q_s . K^T) per skill
__device__ float tea[2*NSK*DVX*2];    // interleaved (e,a) per interaction id
__device__ float qW[NSK*HHX];         // skill_embed[s] @ W1_top + b1

// ============================================================================
// Kernel 0: build all tables (unchanged round-5 structure).
//   [0,125)   role A: tw    (8 skills/block)
//   [125,375) role B: tea   (8 vis/block)
//   [375,407) role C: qW    (32 skills/block)
// ============================================================================
__global__ __launch_bounds__(256) void k0_tables(
    const float* __restrict__ skill_embed,
    const float* __restrict__ key_memory,
    const float* __restrict__ interaction_embed,
    const float* __restrict__ erase_W,
    const float* __restrict__ erase_b,
    const float* __restrict__ add_W,
    const float* __restrict__ add_b,
    const float* __restrict__ fc1_W,
    const float* __restrict__ fc1_b)
{
    extern __shared__ float smem[];
    int tid  = threadIdx.x;
    int w    = tid >> 5;
    int lane = tid & 31;
    int bid  = blockIdx.x;

    if (bid < 125) {
        float* sKt = smem;            // [64][52]
        float* sq  = sKt + DKX*52;    // [8 warps][64]
        for (int idx = tid; idx < MM*DKX; idx += 256) {
            int m = idx / DKX, i = idx % DKX;
            sKt[i*52 + m] = key_memory[m*DKX + i];
        }
        __syncthreads();
        int s = bid*8 + w;
        float* mq = sq + w*64;
        mq[lane]    = skill_embed[s*DKX + lane];
        mq[lane+32] = skill_embed[s*DKX + lane+32];
        __syncwarp();
        const bool v1 = (lane + 32) < MM;
        float d0 = 0.f, d1 = 0.f;
        #pragma unroll 8
        for (int i = 0; i < DKX; i++) {
            float qi = mq[i];
            d0 = fmaf(qi, sKt[i*52 + lane], d0);
            d1 = fmaf(qi, sKt[i*52 + lane + 32], d1);
        }
        float mx = fmaxf(d0, v1 ? d1 : -1e30f);
        #pragma unroll
        for (int off = 16; off > 0; off >>= 1)
            mx = fmaxf(mx, __shfl_xor_sync(0xffffffffu, mx, off));
        float x0 = __expf(d0 - mx);
        float x1 = v1 ? __expf(d1 - mx) : 0.f;
        float sm = x0 + x1;
        #pragma unroll
        for (int off = 16; off > 0; off >>= 1)
            sm += __shfl_xor_sync(0xffffffffu, sm, off);
        float inv = 1.f / sm;
        tw[s*MM + lane] = x0 * inv;
        if (v1) tw[s*MM + lane + 32] = x1 * inv;
    } else if (bid < 375) {
        float* seW = smem;
        float* saW = seW + DKX*DVX;
        float* sv  = saW + DKX*DVX;
        for (int idx = tid; idx < DKX*DVX; idx += 256) {
            seW[idx] = erase_W[idx];
            saW[idx] = add_W[idx];
        }
        __syncthreads();
        int vi = (bid - 125)*8 + w;
        float* mv = sv + w*64;
        mv[lane]    = interaction_embed[vi*DVX + lane];
        mv[lane+32] = interaction_embed[vi*DVX + lane+32];
        __syncwarp();
        float E0 = erase_b[lane], E1 = erase_b[lane+32];
        float A0 = add_b[lane],   A1 = add_b[lane+32];
        #pragma unroll 8
        for (int i = 0; i < DVX; i++) {
            float vv = mv[i];
            E0 = fmaf(vv, seW[i*DVX + lane],    E0);
            E1 = fmaf(vv, seW[i*DVX + lane+32], E1);
            A0 = fmaf(vv, saW[i*DVX + lane],    A0);
            A1 = fmaf(vv, saW[i*DVX + lane+32], A1);
        }
        float2 ea0 = make_float2(1.f/(1.f + __expf(-E0)), tanhf(A0));
        float2 ea1 = make_float2(1.f/(1.f + __expf(-E1)), tanhf(A1));
        *(float2*)&tea[(vi*DVX + lane)*2]      = ea0;
        *(float2*)&tea[(vi*DVX + lane+32)*2]   = ea1;
    } else {
        float* sW1t = smem;            // [64][128]
        float* sb1  = sW1t + 64*HHX;
        float* sq   = sb1 + HHX;       // [8 warps][256]
        for (int idx = tid; idx < 64*HHX; idx += 256) sW1t[idx] = fc1_W[idx];
        if (tid < HHX) sb1[tid] = fc1_b[tid];
        __syncthreads();
        int sbase = (bid - 375)*32 + w*4;
        float* mq = sq + w*256;
        #pragma unroll
        for (int k = 0; k < 4; k++) {
            int s = sbase + k; if (s >= NSK) s = NSK-1;
            mq[lane*4 + k]      = skill_embed[s*DKX + lane];
            mq[(lane+32)*4 + k] = skill_embed[s*DKX + lane+32];
        }
        __syncwarp();
        u64 acc2[4][2];
        #pragma unroll
        for (int c = 0; c < 4; c++) {
            u64 bb = pkd(sb1[lane*4 + c]);
            acc2[c][0] = bb; acc2[c][1] = bb;
        }
        #pragma unroll 4
        for (int i = 0; i < DKX; i++) {
            u64 q01 = *(const u64*)&mq[i*4];
            u64 q23 = *(const u64*)&mq[i*4 + 2];
            float4 w4 = *(const float4*)&sW1t[i*HHX + lane*4];
            u64 wx = pkd(w4.x), wy = pkd(w4.y), wz = pkd(w4.z), wq = pkd(w4.w);
            acc2[0][0] = ffma2(q01, wx, acc2[0][0]);
            acc2[0][1] = ffma2(q23, wx, acc2[0][1]);
            acc2[1][0] = ffma2(q01, wy, acc2[1][0]);
            acc2[1][1] = ffma2(q23, wy, acc2[1][1]);
            acc2[2][0] = ffma2(q01, wz, acc2[2][0]);
            acc2[2][1] = ffma2(q23, wz, acc2[2][1]);
            acc2[3][0] = ffma2(q01, wq, acc2[3][0]);
            acc2[3][1] = ffma2(q23, wq, acc2[3][1]);
        }
        float A[4][4];
        #pragma unroll
        for (int c = 0; c < 4; c++) {
            up2(acc2[c][0], A[c][0], A[c][1]);
            up2(acc2[c][1], A[c][2], A[c][3]);
        }
        #pragma unroll
        for (int k = 0; k < 4; k++) {
            int s = sbase + k;
            if (s < NSK) {
                float4 o = make_float4(A[0][k], A[1][k], A[2][k], A[3][k]);
                *(float4*)&qW[s*HHX + lane*4] = o;
            }
        }
    }
}

// ============================================================================
// Kernel 23: FUSED scan + MLP. One block per batch, 192 threads (6 warps).
// Two scan warps (SMSP-balanced by block parity of bid/148), each fully
// autonomous over 32 columns (25 f32x2 mem pairs/thread, own w smem buffer,
// __syncwarp only). Reads written transposed to smem sread[col][item].
// Every 48 steps: 2 block barriers, 6 warps run the chunk's MLP (8 items
// each) reading x directly from sread, acc seeded from qW. No g_read.
// ============================================================================
#define CHUNK 48
#define ISTR  50    // sread item stride (even, >= CHUNK)

// smem float offsets
#define OFF_W1    0
#define OFF_W2    (64*HHX)               // 8192
#define OFF_SREAD (OFF_W2 + HHX)         // 8320
#define OFF_SWB   (OFF_SREAD + 64*ISTR)  // 11520
#define OFF_IDX   (OFF_SWB + 2*2*56)     // 11744 (ss:200 ints, svi:200 ints)
#define SMEM_FLTS (OFF_IDX + 2*TT)       // 12144

__global__ __launch_bounds__(192,4) void k23_fused(
    const float* __restrict__ value_init,
    const int*   __restrict__ skill_seq,
    const int*   __restrict__ correct_seq,
    const float* __restrict__ mask,
    const float* __restrict__ fc1_W,
    const float* __restrict__ fc2_W,
    const float* __restrict__ fc2_b,
    float*       __restrict__ out)
{
    extern __shared__ float smem[];
    float* sW1   = smem + OFF_W1;     // [64][128] fc1_W rows 64..127
    float* sw2   = smem + OFF_W2;     // [128]
    float* sread = smem + OFF_SREAD;  // [64 cols][ISTR items]
    float* swb   = smem + OFF_SWB;    // [2 scan warps][2 bufs][56]
    int*   ss    = (int*)(smem + OFF_IDX);
    int*   svi   = ss + TT;

    int b    = blockIdx.x;
    int tid  = threadIdx.x;
    int w    = tid >> 5;
    int lane = tid & 31;
    const int base = b * TT;

    // cooperative loads
    for (int idx = tid; idx < 64*HHX; idx += 192) sW1[idx] = fc1_W[64*HHX + idx];
    if (tid < HHX) sw2[tid] = fc2_W[tid];
    for (int i = tid; i < TT; i += 192) {
        int s = skill_seq[base + i];
        ss[i]  = s;
        svi[i] = s + correct_seq[base + i]*NSK;
    }
    __syncthreads();

    // scan warp designation: balance across SMSPs (co-resident blocks differ by 148)
    int sb = ((b / 148) & 1) * 2;            // scan warps = {sb, sb+1}
    bool is_scan = (w == sb) || (w == sb + 1);
    int scan_wid = w - sb;                   // 0 or 1 when is_scan
    int v = scan_wid*32 + lane;              // owned DV column

    u64 mem[25];
    float wA0 = 0.f, wA1 = 0.f, wB0 = 0.f, wB1 = 0.f;
    float2 eaA = make_float2(0.f, 0.f), eaB = eaA;
    if (is_scan) {
        #pragma unroll
        for (int m = 0; m < 25; m++)
            mem[m] = pk2(value_init[(2*m)*DVX + v], value_init[(2*m+1)*DVX + v]);
        // depth-2 prefetch prime
        int s0 = ss[0], vi0 = svi[0];
        wA0 = tw[s0*MM + lane];
        wA1 = (lane < 18) ? tw[s0*MM + 32 + lane] : 0.f;
        eaA = *(const float2*)&tea[(vi0*DVX + v)*2];
        int s1 = ss[1], vi1 = svi[1];
        wB0 = tw[s1*MM + lane];
        wB1 = (lane < 18) ? tw[s1*MM + 32 + lane] : 0.f;
        eaB = *(const float2*)&tea[(vi1*DVX + v)*2];
    }

    float b2 = fc2_b[0];
    float4 w2v = *(const float4*)&sw2[lane*4];

    int t = 0;
    for (int c0 = 0; c0 < TT; c0 += CHUNK) {
        int clen = (TT - c0 < CHUNK) ? (TT - c0) : CHUNK;

        // ---- scan phase (scan warps only) ----
        if (is_scan) {
            float* wbuf = swb + scan_wid*112;
            for (int tl = 0; tl < clen; tl++, t++) {
                float* wb = wbuf + (t & 1)*56;
                wb[lane] = wA0;
                if (lane < 18) wb[32 + lane] = wA1;
                float e = eaA.x, a = eaA.y;
                wA0 = wB0; wA1 = wB1; eaA = eaB;
                __syncwarp();
                if (t + 2 < TT) {
                    int s2 = ss[t+2], vi2 = svi[t+2];
                    wB0 = tw[s2*MM + lane];
                    wB1 = (lane < 18) ? tw[s2*MM + 32 + lane] : 0.f;
                    eaB = *(const float2*)&tea[(vi2*DVX + v)*2];
                }
                u64 nee = pkd(-e);
                u64 aa  = pkd(a);
                u64 r[4] = {0ull,0ull,0ull,0ull};
                #pragma unroll
                for (int i = 0; i < 12; i++) {
                    float4 w4 = *(const float4*)&wb[4*i];
                    u64 wlo = pk2(w4.x, w4.y);
                    u64 whi = pk2(w4.z, w4.w);
                    int m = 2*i;
                    r[m & 3]     = ffma2(wlo, mem[m],   r[m & 3]);
                    u64 t1       = ffma2(mem[m],   nee, aa);
                    mem[m]       = ffma2(wlo, t1,  mem[m]);
                    r[(m+1) & 3] = ffma2(whi, mem[m+1], r[(m+1) & 3]);
                    u64 t2       = ffma2(mem[m+1], nee, aa);
                    mem[m+1]     = ffma2(whi, t2,  mem[m+1]);
                }
                {
                    u64 ww = *(const u64*)&wb[48];
                    r[0]    = ffma2(ww, mem[24], r[0]);
                    u64 t1  = ffma2(mem[24], nee, aa);
                    mem[24] = ffma2(ww, t1, mem[24]);
                }
                float x0, x1, y0, y1, z0, z1, u0, u1;
                up2(r[0], x0, x1); up2(r[1], y0, y1);
                up2(r[2], z0, z1); up2(r[3], u0, u1);
                sread[v*ISTR + tl] = ((x0+x1) + (y0+y1)) + ((z0+z1) + (u0+u1));
            }
        } else {
            t += clen;
        }
        __syncthreads();   // reads of this chunk visible to all

        // ---- MLP phase (all 6 warps, 8 items each) ----
        if (w*8 < clen) {
            int l0 = w*8;              // local item base (even)
            int t0 = c0 + l0;
            float4 qk[8];
            #pragma unroll
            for (int k = 0; k < 8; k++) {
                int s = ss[t0 + k];
                qk[k] = *(const float4*)&qW[s*HHX + lane*4];
            }
            u64 acc[4][4];   // [c][item-pair]
            #pragma unroll
            for (int kk = 0; kk < 4; kk++) {
                acc[0][kk] = pk2(qk[2*kk].x, qk[2*kk+1].x);
                acc[1][kk] = pk2(qk[2*kk].y, qk[2*kk+1].y);
                acc[2][kk] = pk2(qk[2*kk].z, qk[2*kk+1].z);
                acc[3][kk] = pk2(qk[2*kk].w, qk[2*kk+1].w);
            }
            #pragma unroll 4
            for (int j = 0; j < 64; j++) {
                float4 wv = *(const float4*)&sW1[j*HHX + lane*4];
                u64 xp[4];
                #pragma unroll
                for (int kk = 0; kk < 4; kk++)
                    xp[kk] = *(const u64*)&sread[j*ISTR + l0 + 2*kk];
                u64 wx = pkd(wv.x), wy = pkd(wv.y), wz = pkd(wv.z), wq = pkd(wv.w);
                #pragma unroll
                for (int kk = 0; kk < 4; kk++) {
                    acc[0][kk] = ffma2(xp[kk], wx, acc[0][kk]);
                    acc[1][kk] = ffma2(xp[kk], wy, acc[1][kk]);
                    acc[2][kk] = ffma2(xp[kk], wz, acc[2][kk]);
                    acc[3][kk] = ffma2(xp[kk], wq, acc[3][kk]);
                }
            }
            float hv[4][8];
            #pragma unroll
            for (int c = 0; c < 4; c++) {
                #pragma unroll
                for (int kk = 0; kk < 4; kk++)
                    up2(acc[c][kk], hv[c][2*kk], hv[c][2*kk+1]);
            }
            float part[8];
            #pragma unroll
            for (int k = 0; k < 8; k++) {
                float p = 0.f;
                #pragma unroll
                for (int c = 0; c < 4; c++) {
                    float h = fmaxf(hv[c][k], 0.f);
                    p = fmaf(h, w2v.x * 0.f + sw2[lane*4 + c], p);  // use smem (w2v kept for regs)
                }
                part[k] = p;
            }
            #pragma unroll
            for (int off = 16; off > 0; off >>= 1) {
                #pragma unroll
                for (int k = 0; k < 8; k++)
                    part[k] += __shfl_xor_sync(0xffffffffu, part[k], off);
            }
            if (lane < 8) {
                int item = base + t0 + lane;
                float logit = part[lane] + b2;
                float p = 1.f / (1.f + __expf(-logit));
                float mk = mask[item];
                out[item]          = p * mk;
                out[NITEMS + item] = (float)correct_seq[item] * mk;
            }
        }
        __syncthreads();   // sread free for next chunk
    }
}

// ============================================================================
extern "C" void kernel_launch(void* const* d_in, const int* in_sizes, int n_in,
                              void* d_out, int out_size) {
    const int*   skill_seq         = (const int*)  d_in[0];
    const int*   correct_seq       = (const int*)  d_in[1];
    const float* mask              = (const float*)d_in[2];
    const float* skill_embed       = (const float*)d_in[3];
    const float* key_memory        = (const float*)d_in[4];
    const float* value_init        = (const float*)d_in[5];
    const float* interaction_embed = (const float*)d_in[6];
    const float* erase_W           = (const float*)d_in[7];
    const float* erase_b           = (const float*)d_in[8];
    const float* add_W             = (const float*)d_in[9];
    const float* add_b             = (const float*)d_in[10];
    const float* fc1_W             = (const float*)d_in[11];
    const float* fc1_b             = (const float*)d_in[12];
    const float* fc2_W             = (const float*)d_in[13];
    const float* fc2_b             = (const float*)d_in[14];
    float* out = (float*)d_out;

    const int k0_smem  = (64*HHX + HHX + 8*256) * sizeof(float);   // ~41.5 KB
    const int k23_smem = SMEM_FLTS * sizeof(float);                // ~48.6 KB
    cudaFuncSetAttribute(k23_fused, cudaFuncAttributeMaxDynamicSharedMemorySize, k23_smem);

    k0_tables<<<407, 256, k0_smem>>>(skill_embed, key_memory, interaction_embed,
                                     erase_W, erase_b, add_W, add_b, fc1_W, fc1_b);
    k23_fused<<<BB, 192, k23_smem>>>(value_init, skill_seq, correct_seq, mask,
                                     fc1_W, fc2_W, fc2_b, out);
}

// round 7
// speedup vs baseline: 1.8131x; 1.8131x over previous
#include <cuda_runtime.h>

#define BB 512
#define TT 200
#define MM 50
#define DKX 64
#define DVX 64
#define HHX 128
#define NSK 1000
#define NITEMS (BB*TT)

typedef unsigned long long u64;

// ---- packed f32x2 helpers ----
__device__ __forceinline__ u64 pk2(float lo, float hi) {
    u64 r; asm("mov.b64 %0,{%1,%2};" : "=l"(r) : "f"(lo), "f"(hi)); return r;
}
__device__ __forceinline__ u64 pkd(float x) {
    u64 r; asm("mov.b64 %0,{%1,%1};" : "=l"(r) : "f"(x)); return r;
}
__device__ __forceinline__ void up2(u64 v, float& lo, float& hi) {
    asm("mov.b64 {%0,%1},%2;" : "=f"(lo), "=f"(hi) : "l"(v));
}
__device__ __forceinline__ u64 ffma2(u64 a, u64 b, u64 c) {
    u64 d; asm("fma.rn.f32x2 %0,%1,%2,%3;" : "=l"(d) : "l"(a), "l"(b), "l"(c)); return d;
}

// ---- tables + scratch ----
__device__ float tw[NSK*MM];          // softmax(q_s . K^T) per skill
__device__ float tea[2*NSK*DVX*2];    // interleaved (e,a) per interaction id
__device__ float qW[NSK*HHX];         // skill_embed[s] @ W1_top + b1
__device__ float g_read[NITEMS*DVX];

// ============================================================================
// Kernel 0: build all tables (round-5, known good).
//   [0,125)   role A: tw    (8 skills/block)
//   [125,375) role B: tea   (8 vis/block)
//   [375,407) role C: qW    (32 skills/block)
// ============================================================================
__global__ __launch_bounds__(256) void k0_tables(
    const float* __restrict__ skill_embed,
    const float* __restrict__ key_memory,
    const float* __restrict__ interaction_embed,
    const float* __restrict__ erase_W,
    const float* __restrict__ erase_b,
    const float* __restrict__ add_W,
    const float* __restrict__ add_b,
    const float* __restrict__ fc1_W,
    const float* __restrict__ fc1_b)
{
    extern __shared__ float smem[];
    int tid  = threadIdx.x;
    int w    = tid >> 5;
    int lane = tid & 31;
    int bid  = blockIdx.x;

    if (bid < 125) {
        float* sKt = smem;            // [64][52]
        float* sq  = sKt + DKX*52;    // [8 warps][64]
        for (int idx = tid; idx < MM*DKX; idx += 256) {
            int m = idx / DKX, i = idx % DKX;
            sKt[i*52 + m] = key_memory[m*DKX + i];
        }
        __syncthreads();
        int s = bid*8 + w;
        float* mq = sq + w*64;
        mq[lane]    = skill_embed[s*DKX + lane];
        mq[lane+32] = skill_embed[s*DKX + lane+32];
        __syncwarp();
        const bool v1 = (lane + 32) < MM;
        float d0 = 0.f, d1 = 0.f;
        #pragma unroll 8
        for (int i = 0; i < DKX; i++) {
            float qi = mq[i];
            d0 = fmaf(qi, sKt[i*52 + lane], d0);
            d1 = fmaf(qi, sKt[i*52 + lane + 32], d1);
        }
        float mx = fmaxf(d0, v1 ? d1 : -1e30f);
        #pragma unroll
        for (int off = 16; off > 0; off >>= 1)
            mx = fmaxf(mx, __shfl_xor_sync(0xffffffffu, mx, off));
        float x0 = __expf(d0 - mx);
        float x1 = v1 ? __expf(d1 - mx) : 0.f;
        float sm = x0 + x1;
        #pragma unroll
        for (int off = 16; off > 0; off >>= 1)
            sm += __shfl_xor_sync(0xffffffffu, sm, off);
        float inv = 1.f / sm;
        tw[s*MM + lane] = x0 * inv;
        if (v1) tw[s*MM + lane + 32] = x1 * inv;
    } else if (bid < 375) {
        float* seW = smem;
        float* saW = seW + DKX*DVX;
        float* sv  = saW + DKX*DVX;
        for (int idx = tid; idx < DKX*DVX; idx += 256) {
            seW[idx] = erase_W[idx];
            saW[idx] = add_W[idx];
        }
        __syncthreads();
        int vi = (bid - 125)*8 + w;
        float* mv = sv + w*64;
        mv[lane]    = interaction_embed[vi*DVX + lane];
        mv[lane+32] = interaction_embed[vi*DVX + lane+32];
        __syncwarp();
        float E0 = erase_b[lane], E1 = erase_b[lane+32];
        float A0 = add_b[lane],   A1 = add_b[lane+32];
        #pragma unroll 8
        for (int i = 0; i < DVX; i++) {
            float vv = mv[i];
            E0 = fmaf(vv, seW[i*DVX + lane],    E0);
            E1 = fmaf(vv, seW[i*DVX + lane+32], E1);
            A0 = fmaf(vv, saW[i*DVX + lane],    A0);
            A1 = fmaf(vv, saW[i*DVX + lane+32], A1);
        }
        float2 ea0 = make_float2(1.f/(1.f + __expf(-E0)), tanhf(A0));
        float2 ea1 = make_float2(1.f/(1.f + __expf(-E1)), tanhf(A1));
        *(float2*)&tea[(vi*DVX + lane)*2]      = ea0;
        *(float2*)&tea[(vi*DVX + lane+32)*2]   = ea1;
    } else {
        float* sW1t = smem;            // [64][128]
        float* sb1  = sW1t + 64*HHX;
        float* sq   = sb1 + HHX;       // [8 warps][256]
        for (int idx = tid; idx < 64*HHX; idx += 256) sW1t[idx] = fc1_W[idx];
        if (tid < HHX) sb1[tid] = fc1_b[tid];
        __syncthreads();
        int sbase = (bid - 375)*32 + w*4;
        float* mq = sq + w*256;
        #pragma unroll
        for (int k = 0; k < 4; k++) {
            int s = sbase + k; if (s >= NSK) s = NSK-1;
            mq[lane*4 + k]      = skill_embed[s*DKX + lane];
            mq[(lane+32)*4 + k] = skill_embed[s*DKX + lane+32];
        }
        __syncwarp();
        u64 acc2[4][2];
        #pragma unroll
        for (int c = 0; c < 4; c++) {
            u64 bb = pkd(sb1[lane*4 + c]);
            acc2[c][0] = bb; acc2[c][1] = bb;
        }
        #pragma unroll 4
        for (int i = 0; i < DKX; i++) {
            u64 q01 = *(const u64*)&mq[i*4];
            u64 q23 = *(const u64*)&mq[i*4 + 2];
            float4 w4 = *(const float4*)&sW1t[i*HHX + lane*4];
            u64 wx = pkd(w4.x), wy = pkd(w4.y), wz = pkd(w4.z), wq = pkd(w4.w);
            acc2[0][0] = ffma2(q01, wx, acc2[0][0]);
            acc2[0][1] = ffma2(q23, wx, acc2[0][1]);
            acc2[1][0] = ffma2(q01, wy, acc2[1][0]);
            acc2[1][1] = ffma2(q23, wy, acc2[1][1]);
            acc2[2][0] = ffma2(q01, wz, acc2[2][0]);
            acc2[2][1] = ffma2(q23, wz, acc2[2][1]);
            acc2[3][0] = ffma2(q01, wq, acc2[3][0]);
            acc2[3][1] = ffma2(q23, wq, acc2[3][1]);
        }
        float A[4][4];
        #pragma unroll
        for (int c = 0; c < 4; c++) {
            up2(acc2[c][0], A[c][0], A[c][1]);
            up2(acc2[c][1], A[c][2], A[c][3]);
        }
        #pragma unroll
        for (int k = 0; k < 4; k++) {
            int s = sbase + k;
            if (s < NSK) {
                float4 o = make_float4(A[0][k], A[1][k], A[2][k], A[3][k]);
                *(float4*)&qW[s*HHX + lane*4] = o;
            }
        }
    }
}

// ============================================================================
// Kernel 2: sequential memory scan. One block per batch, 64 threads.
// NEW: the ENTIRE w schedule (200 steps x 50) is gathered into smem up-front
// (one overlapped burst) -> the 200-step loop has NO stores, NO block syncs,
// NO w prefetching. Per step: 13 LDS + 1 (e,a) reg + 38 FFMA2.
// tea stays depth-2 prefetched from L2.
// ============================================================================
__global__ __launch_bounds__(64) void k2_scan(
    const float* __restrict__ value_init,
    const int*   __restrict__ skill_seq,
    const int*   __restrict__ correct_seq)
{
    __shared__ __align__(16) float sw[TT*52];   // 41.6 KB: per-step w rows (stride 52)
    __shared__ int ss[TT];
    __shared__ int svi[TT];
    int b = blockIdx.x;
    int v = threadIdx.x;          // 0..63 = DV column
    const int base = b * TT;

    for (int i = v; i < TT; i += 64) {
        int s = skill_seq[base + i];
        ss[i]  = s;
        svi[i] = s + correct_seq[base + i]*NSK;
    }
    __syncthreads();

    // gather the whole w schedule (L2-hot rows of tw); pads zeroed
    for (int idx = v; idx < TT*MM; idx += 64) {
        int t = idx / MM, j = idx - t*MM;
        sw[t*52 + j] = tw[ss[t]*MM + j];
    }
    for (int i = v; i < TT; i += 64) { sw[i*52 + 50] = 0.f; sw[i*52 + 51] = 0.f; }

    u64 mem[25];
    #pragma unroll
    for (int m = 0; m < 25; m++)
        mem[m] = pk2(value_init[(2*m)*DVX + v], value_init[(2*m+1)*DVX + v]);

    // depth-2 prefetch of (e,a) only
    float2 eaA = *(const float2*)&tea[(svi[0]*DVX + v)*2];
    float2 eaB = *(const float2*)&tea[(svi[1]*DVX + v)*2];
    __syncthreads();   // sw visible

    for (int t = 0; t < TT; t++) {
        float e = eaA.x, a = eaA.y;
        eaA = eaB;
        if (t + 2 < TT)
            eaB = *(const float2*)&tea[(svi[t+2]*DVX + v)*2];
        u64 nee = pkd(-e);
        u64 aa  = pkd(a);
        const float* wr = &sw[t*52];
        u64 r[4] = {0ull,0ull,0ull,0ull};
        #pragma unroll
        for (int i = 0; i < 12; i++) {          // pairs 2i, 2i+1 via LDS.128
            float4 w4 = *(const float4*)&wr[4*i];
            u64 wlo = pk2(w4.x, w4.y);
            u64 whi = pk2(w4.z, w4.w);
            int m = 2*i;
            r[m & 3]     = ffma2(wlo, mem[m],   r[m & 3]);
            u64 t1       = ffma2(mem[m],   nee, aa);
            mem[m]       = ffma2(wlo, t1,  mem[m]);
            r[(m+1) & 3] = ffma2(whi, mem[m+1], r[(m+1) & 3]);
            u64 t2       = ffma2(mem[m+1], nee, aa);
            mem[m+1]     = ffma2(whi, t2,  mem[m+1]);
        }
        {   // pair 24
            u64 ww = *(const u64*)&wr[48];
            r[0]    = ffma2(ww, mem[24], r[0]);
            u64 t1  = ffma2(mem[24], nee, aa);
            mem[24] = ffma2(ww, t1, mem[24]);
        }
        float x0, x1, y0, y1, z0, z1, u0, u1;
        up2(r[0], x0, x1); up2(r[1], y0, y1);
        up2(r[2], z0, z1); up2(r[3], u0, u1);
        g_read[(base + t)*DVX + v] = ((x0+x1) + (y0+y1)) + ((z0+z1) + (u0+u1));
    }
}

// ============================================================================
// Kernel 3: output MLP, read-half only (round-5, known good).
// ============================================================================
__global__ __launch_bounds__(256,3) void k3_mlp(
    const int*   __restrict__ skill_seq,
    const int*   __restrict__ correct_seq,
    const float* __restrict__ mask,
    const float* __restrict__ fc1_W,
    const float* __restrict__ fc2_W,
    const float* __restrict__ fc2_b,
    float*       __restrict__ out)
{
    extern __shared__ float smem[];
    float* sW1 = smem;                    // [64][128] = fc1_W rows 64..127
    float* sw2 = sW1 + 64*HHX;            // [128]
    float* sx  = sw2 + HHX;               // [8 warps][64*10]

    int tid = threadIdx.x;
    for (int idx = tid; idx < 64*HHX; idx += 256) sW1[idx] = fc1_W[64*HHX + idx];
    if (tid < HHX) sw2[tid] = fc2_W[tid];
    __syncthreads();
    float b2 = fc2_b[0];

    int w    = tid >> 5;
    int lane = tid & 31;
    float* myx = sx + w * (64 * 10);

    const int nwarps  = gridDim.x * 8;
    const int ngroups = NITEMS / 8;

    for (int g = blockIdx.x*8 + w; g < ngroups; g += nwarps) {
        int base = g * 8;
        float4 qk[8];
        #pragma unroll
        for (int k = 0; k < 8; k++) {
            int item = base + k;
            int s = skill_seq[item];
            qk[k] = *(const float4*)&qW[s*HHX + lane*4];
            myx[(lane)    *10 + k] = g_read[item*DVX + lane];
            myx[(lane+32) *10 + k] = g_read[item*DVX + lane+32];
        }
        __syncwarp();

        u64 acc[4][4];   // [c][item-pair]
        #pragma unroll
        for (int kk = 0; kk < 4; kk++) {
            acc[0][kk] = pk2(qk[2*kk].x, qk[2*kk+1].x);
            acc[1][kk] = pk2(qk[2*kk].y, qk[2*kk+1].y);
            acc[2][kk] = pk2(qk[2*kk].z, qk[2*kk+1].z);
            acc[3][kk] = pk2(qk[2*kk].w, qk[2*kk+1].w);
        }
        #pragma unroll 4
        for (int j = 0; j < 64; j++) {
            float4 wv = *(const float4*)&sW1[j*HHX + lane*4];
            u64 xp[4];
            #pragma unroll
            for (int kk = 0; kk < 4; kk++)
                xp[kk] = *(const u64*)&myx[j*10 + 2*kk];
            u64 wx = pkd(wv.x), wy = pkd(wv.y), wz = pkd(wv.z), wq = pkd(wv.w);
            #pragma unroll
            for (int kk = 0; kk < 4; kk++) {
                acc[0][kk] = ffma2(xp[kk], wx, acc[0][kk]);
                acc[1][kk] = ffma2(xp[kk], wy, acc[1][kk]);
                acc[2][kk] = ffma2(xp[kk], wz, acc[2][kk]);
                acc[3][kk] = ffma2(xp[kk], wq, acc[3][kk]);
            }
        }
        float hv[4][8];
        #pragma unroll
        for (int c = 0; c < 4; c++) {
            #pragma unroll
            for (int kk = 0; kk < 4; kk++)
                up2(acc[c][kk], hv[c][2*kk], hv[c][2*kk+1]);
        }
        float part[8];
        #pragma unroll
        for (int k = 0; k < 8; k++) {
            float p = 0.f;
            #pragma unroll
            for (int c = 0; c < 4; c++) {
                float h = fmaxf(hv[c][k], 0.f);
                p = fmaf(h, sw2[lane*4 + c], p);
            }
            part[k] = p;
        }
        #pragma unroll
        for (int off = 16; off > 0; off >>= 1) {
            #pragma unroll
            for (int k = 0; k < 8; k++)
                part[k] += __shfl_xor_sync(0xffffffffu, part[k], off);
        }
        if (lane < 8) {
            int item = base + lane;
            float logit = part[lane] + b2;
            float p = 1.f / (1.f + __expf(-logit));
            float mk = mask[item];
            out[item]          = p * mk;
            out[NITEMS + item] = (float)correct_seq[item] * mk;
        }
        __syncwarp();
    }
}

// ============================================================================
extern "C" void kernel_launch(void* const* d_in, const int* in_sizes, int n_in,
                              void* d_out, int out_size) {
    const int*   skill_seq         = (const int*)  d_in[0];
    const int*   correct_seq       = (const int*)  d_in[1];
    const float* mask              = (const float*)d_in[2];
    const float* skill_embed       = (const float*)d_in[3];
    const float* key_memory        = (const float*)d_in[4];
    const float* value_init        = (const float*)d_in[5];
    const float* interaction_embed = (const float*)d_in[6];
    const float* erase_W           = (const float*)d_in[7];
    const float* erase_b           = (const float*)d_in[8];
    const float* add_W             = (const float*)d_in[9];
    const float* add_b             = (const float*)d_in[10];
    const float* fc1_W             = (const float*)d_in[11];
    const float* fc1_b             = (const float*)d_in[12];
    const float* fc2_W             = (const float*)d_in[13];
    const float* fc2_b             = (const float*)d_in[14];
    float* out = (float*)d_out;

    const int k0_smem = (64*HHX + HHX + 8*256) * sizeof(float);            // ~41.5 KB
    const int k3_smem = (64*HHX + HHX + 8*64*10) * sizeof(float);          // ~53 KB
    cudaFuncSetAttribute(k3_mlp, cudaFuncAttributeMaxDynamicSharedMemorySize, k3_smem);

    k0_tables<<<407, 256, k0_smem>>>(skill_embed, key_memory, interaction_embed,
                                     erase_W, erase_b, add_W, add_b, fc1_W, fc1_b);
    k2_scan<<<BB, 64>>>(value_init, skill_seq, correct_seq);
    k3_mlp<<<444, 256, k3_smem>>>(skill_seq, correct_seq, mask,
                                  fc1_W, fc2_W, fc2_b, out);
}

// round 9
// speedup vs baseline: 2.2351x; 1.2327x over previous
#include <cuda_runtime.h>
#include <cstdint>

#define BB 512
#define TT 200
#define MM 50
#define DKX 64
#define DVX 64
#define HHX 128
#define NSK 1000
#define NITEMS (BB*TT)

typedef unsigned long long u64;
typedef unsigned int u32;

// ---- packed f32x2 helpers ----
__device__ __forceinline__ u64 pk2(float lo, float hi) {
    u64 r; asm("mov.b64 %0,{%1,%2};" : "=l"(r) : "f"(lo), "f"(hi)); return r;
}
__device__ __forceinline__ u64 pkd(float x) {
    u64 r; asm("mov.b64 %0,{%1,%1};" : "=l"(r) : "f"(x)); return r;
}
__device__ __forceinline__ void up2(u64 v, float& lo, float& hi) {
    asm("mov.b64 {%0,%1},%2;" : "=f"(lo), "=f"(hi) : "l"(v));
}
__device__ __forceinline__ u64 ffma2(u64 a, u64 b, u64 c) {
    u64 d; asm("fma.rn.f32x2 %0,%1,%2,%3;" : "=l"(d) : "l"(a), "l"(b), "l"(c)); return d;
}

// ---- tables + scratch ----
__device__ float tw[NSK*MM];          // softmax(q_s . K^T) per skill
__device__ float tea[2*NSK*DVX*2];    // interleaved (e,a) per interaction id
__device__ float qW[NSK*HHX];         // skill_embed[s] @ W1_top + b1
__device__ float g_read[NITEMS*DVX];

// ============================================================================
// Kernel 0: build all tables (round-5, known good).
// ============================================================================
__global__ __launch_bounds__(256) void k0_tables(
    const float* __restrict__ skill_embed,
    const float* __restrict__ key_memory,
    const float* __restrict__ interaction_embed,
    const float* __restrict__ erase_W,
    const float* __restrict__ erase_b,
    const float* __restrict__ add_W,
    const float* __restrict__ add_b,
    const float* __restrict__ fc1_W,
    const float* __restrict__ fc1_b)
{
    extern __shared__ float smem[];
    int tid  = threadIdx.x;
    int w    = tid >> 5;
    int lane = tid & 31;
    int bid  = blockIdx.x;

    if (bid < 125) {
        float* sKt = smem;            // [64][52]
        float* sq  = sKt + DKX*52;    // [8 warps][64]
        for (int idx = tid; idx < MM*DKX; idx += 256) {
            int m = idx / DKX, i = idx % DKX;
            sKt[i*52 + m] = key_memory[m*DKX + i];
        }
        __syncthreads();
        int s = bid*8 + w;
        float* mq = sq + w*64;
        mq[lane]    = skill_embed[s*DKX + lane];
        mq[lane+32] = skill_embed[s*DKX + lane+32];
        __syncwarp();
        const bool v1 = (lane + 32) < MM;
        float d0 = 0.f, d1 = 0.f;
        #pragma unroll 8
        for (int i = 0; i < DKX; i++) {
            float qi = mq[i];
            d0 = fmaf(qi, sKt[i*52 + lane], d0);
            d1 = fmaf(qi, sKt[i*52 + lane + 32], d1);
        }
        float mx = fmaxf(d0, v1 ? d1 : -1e30f);
        #pragma unroll
        for (int off = 16; off > 0; off >>= 1)
            mx = fmaxf(mx, __shfl_xor_sync(0xffffffffu, mx, off));
        float x0 = __expf(d0 - mx);
        float x1 = v1 ? __expf(d1 - mx) : 0.f;
        float sm = x0 + x1;
        #pragma unroll
        for (int off = 16; off > 0; off >>= 1)
            sm += __shfl_xor_sync(0xffffffffu, sm, off);
        float inv = 1.f / sm;
        tw[s*MM + lane] = x0 * inv;
        if (v1) tw[s*MM + lane + 32] = x1 * inv;
    } else if (bid < 375) {
        float* seW = smem;
        float* saW = seW + DKX*DVX;
        float* sv  = saW + DKX*DVX;
        for (int idx = tid; idx < DKX*DVX; idx += 256) {
            seW[idx] = erase_W[idx];
            saW[idx] = add_W[idx];
        }
        __syncthreads();
        int vi = (bid - 125)*8 + w;
        float* mv = sv + w*64;
        mv[lane]    = interaction_embed[vi*DVX + lane];
        mv[lane+32] = interaction_embed[vi*DVX + lane+32];
        __syncwarp();
        float E0 = erase_b[lane], E1 = erase_b[lane+32];
        float A0 = add_b[lane],   A1 = add_b[lane+32];
        #pragma unroll 8
        for (int i = 0; i < DVX; i++) {
            float vv = mv[i];
            E0 = fmaf(vv, seW[i*DVX + lane],    E0);
            E1 = fmaf(vv, seW[i*DVX + lane+32], E1);
            A0 = fmaf(vv, saW[i*DVX + lane],    A0);
            A1 = fmaf(vv, saW[i*DVX + lane+32], A1);
        }
        float2 ea0 = make_float2(1.f/(1.f + __expf(-E0)), tanhf(A0));
        float2 ea1 = make_float2(1.f/(1.f + __expf(-E1)), tanhf(A1));
        *(float2*)&tea[(vi*DVX + lane)*2]      = ea0;
        *(float2*)&tea[(vi*DVX + lane+32)*2]   = ea1;
    } else {
        float* sW1t = smem;            // [64][128]
        float* sb1  = sW1t + 64*HHX;
        float* sq   = sb1 + HHX;       // [8 warps][256]
        for (int idx = tid; idx < 64*HHX; idx += 256) sW1t[idx] = fc1_W[idx];
        if (tid < HHX) sb1[tid] = fc1_b[tid];
        __syncthreads();
        int sbase = (bid - 375)*32 + w*4;
        float* mq = sq + w*256;
        #pragma unroll
        for (int k = 0; k < 4; k++) {
            int s = sbase + k; if (s >= NSK) s = NSK-1;
            mq[lane*4 + k]      = skill_embed[s*DKX + lane];
            mq[(lane+32)*4 + k] = skill_embed[s*DKX + lane+32];
        }
        __syncwarp();
        u64 acc2[4][2];
        #pragma unroll
        for (int c = 0; c < 4; c++) {
            u64 bb = pkd(sb1[lane*4 + c]);
            acc2[c][0] = bb; acc2[c][1] = bb;
        }
        #pragma unroll 4
        for (int i = 0; i < DKX; i++) {
            u64 q01 = *(const u64*)&mq[i*4];
            u64 q23 = *(const u64*)&mq[i*4 + 2];
            float4 w4 = *(const float4*)&sW1t[i*HHX + lane*4];
            u64 wx = pkd(w4.x), wy = pkd(w4.y), wz = pkd(w4.z), wq = pkd(w4.w);
            acc2[0][0] = ffma2(q01, wx, acc2[0][0]);
            acc2[0][1] = ffma2(q23, wx, acc2[0][1]);
            acc2[1][0] = ffma2(q01, wy, acc2[1][0]);
            acc2[1][1] = ffma2(q23, wy, acc2[1][1]);
            acc2[2][0] = ffma2(q01, wz, acc2[2][0]);
            acc2[2][1] = ffma2(q23, wz, acc2[2][1]);
            acc2[3][0] = ffma2(q01, wq, acc2[3][0]);
            acc2[3][1] = ffma2(q23, wq, acc2[3][1]);
        }
        float A[4][4];
        #pragma unroll
        for (int c = 0; c < 4; c++) {
            up2(acc2[c][0], A[c][0], A[c][1]);
            up2(acc2[c][1], A[c][2], A[c][3]);
        }
        #pragma unroll
        for (int k = 0; k < 4; k++) {
            int s = sbase + k;
            if (s < NSK) {
                float4 o = make_float4(A[0][k], A[1][k], A[2][k], A[3][k]);
                *(float4*)&qW[s*HHX + lane*4] = o;
            }
        }
    }
}

// ============================================================================
// Kernel 2: sequential memory scan. One block per batch, 64 threads.
// Whole w schedule gathered via cp.async (LDGSTS: no register round-trip,
// no dependent latency) -> steady-state loop has NO stores, NO block syncs,
// NO w prefetch. Per step: 13 LDS + 1 (e,a) prefetch + 38 FFMA2.
// ============================================================================
__global__ __launch_bounds__(64) void k2_scan(
    const float* __restrict__ value_init,
    const int*   __restrict__ skill_seq,
    const int*   __restrict__ correct_seq)
{
    __shared__ __align__(16) float sw[TT*52];   // 41.6 KB: per-step w rows (stride 52)
    __shared__ int ss[TT];
    __shared__ int svi[TT];
    int b = blockIdx.x;
    int v = threadIdx.x;          // 0..63 = DV column
    const int base = b * TT;

    for (int i = v; i < TT; i += 64) {
        int s = skill_seq[base + i];
        ss[i]  = s;
        svi[i] = s + correct_seq[base + i]*NSK;
    }
    __syncthreads();

    // ---- cp.async gather of the whole w schedule (issue-bound) ----
    {
        int wp = v >> 5, lane = v & 31;
        if (lane < 25) {
            for (int t = wp; t < TT; t += 2) {
                u32 dst = (u32)__cvta_generic_to_shared(&sw[t*52 + lane*2]);
                const float* src = &tw[ss[t]*MM + lane*2];
                asm volatile("cp.async.ca.shared.global [%0], [%1], 8;"
                             :: "r"(dst), "l"(src));
            }
        }
        // zero the pad floats 50,51 of each row
        for (int i = v; i < TT; i += 64) { sw[i*52 + 50] = 0.f; sw[i*52 + 51] = 0.f; }
        asm volatile("cp.async.commit_group;");
    }

    u64 mem[25];
    #pragma unroll
    for (int m = 0; m < 25; m++)
        mem[m] = pk2(value_init[(2*m)*DVX + v], value_init[(2*m+1)*DVX + v]);

    // depth-2 prefetch of (e,a)
    float2 eaA = *(const float2*)&tea[(svi[0]*DVX + v)*2];
    float2 eaB = *(const float2*)&tea[(svi[1]*DVX + v)*2];

    asm volatile("cp.async.wait_group 0;" ::: "memory");
    __syncthreads();   // sw visible block-wide

    for (int t = 0; t < TT; t++) {
        float e = eaA.x, a = eaA.y;
        eaA = eaB;
        if (t + 2 < TT)
            eaB = *(const float2*)&tea[(svi[t+2]*DVX + v)*2];
        u64 nee = pkd(-e);
        u64 aa  = pkd(a);
        const float* wr = &sw[t*52];
        u64 r[4] = {0ull,0ull,0ull,0ull};
        #pragma unroll
        for (int i = 0; i < 12; i++) {          // pairs 2i, 2i+1 via LDS.128
            float4 w4 = *(const float4*)&wr[4*i];
            u64 wlo = pk2(w4.x, w4.y);
            u64 whi = pk2(w4.z, w4.w);
            int m = 2*i;
            r[m & 3]     = ffma2(wlo, mem[m],   r[m & 3]);
            u64 t1       = ffma2(mem[m],   nee, aa);
            mem[m]       = ffma2(wlo, t1,  mem[m]);
            r[(m+1) & 3] = ffma2(whi, mem[m+1], r[(m+1) & 3]);
            u64 t2       = ffma2(mem[m+1], nee, aa);
            mem[m+1]     = ffma2(whi, t2,  mem[m+1]);
        }
        {   // pair 24
            u64 ww = *(const u64*)&wr[48];
            r[0]    = ffma2(ww, mem[24], r[0]);
            u64 t1  = ffma2(mem[24], nee, aa);
            mem[24] = ffma2(ww, t1, mem[24]);
        }
        float x0, x1, y0, y1, z0, z1, u0, u1;
        up2(r[0], x0, x1); up2(r[1], y0, y1);
        up2(r[2], z0, z1); up2(r[3], u0, u1);
        g_read[(base + t)*DVX + v] = ((x0+x1) + (y0+y1)) + ((z0+z1) + (u0+u1));
    }
}

// ============================================================================
// Kernel 3: output MLP, read-half only (round-5, known good).
// ============================================================================
__global__ __launch_bounds__(256,3) void k3_mlp(
    const int*   __restrict__ skill_seq,
    const int*   __restrict__ correct_seq,
    const float* __restrict__ mask,
    const float* __restrict__ fc1_W,
    const float* __restrict__ fc2_W,
    const float* __restrict__ fc2_b,
    float*       __restrict__ out)
{
    extern __shared__ float smem[];
    float* sW1 = smem;                    // [64][128] = fc1_W rows 64..127
    float* sw2 = sW1 + 64*HHX;            // [128]
    float* sx  = sw2 + HHX;               // [8 warps][64*10]

    int tid = threadIdx.x;
    for (int idx = tid; idx < 64*HHX; idx += 256) sW1[idx] = fc1_W[64*HHX + idx];
    if (tid < HHX) sw2[tid] = fc2_W[tid];
    __syncthreads();
    float b2 = fc2_b[0];

    int w    = tid >> 5;
    int lane = tid & 31;
    float* myx = sx + w * (64 * 10);

    const int nwarps  = gridDim.x * 8;
    const int ngroups = NITEMS / 8;

    for (int g = blockIdx.x*8 + w; g < ngroups; g += nwarps) {
        int base = g * 8;
        float4 qk[8];
        #pragma unroll
        for (int k = 0; k < 8; k++) {
            int item = base + k;
            int s = skill_seq[item];
            qk[k] = *(const float4*)&qW[s*HHX + lane*4];
            myx[(lane)    *10 + k] = g_read[item*DVX + lane];
            myx[(lane+32) *10 + k] = g_read[item*DVX + lane+32];
        }
        __syncwarp();

        u64 acc[4][4];   // [c][item-pair]
        #pragma unroll
        for (int kk = 0; kk < 4; kk++) {
            acc[0][kk] = pk2(qk[2*kk].x, qk[2*kk+1].x);
            acc[1][kk] = pk2(qk[2*kk].y, qk[2*kk+1].y);
            acc[2][kk] = pk2(qk[2*kk].z, qk[2*kk+1].z);
            acc[3][kk] = pk2(qk[2*kk].w, qk[2*kk+1].w);
        }
        #pragma unroll 4
        for (int j = 0; j < 64; j++) {
            float4 wv = *(const float4*)&sW1[j*HHX + lane*4];
            u64 xp[4];
            #pragma unroll
            for (int kk = 0; kk < 4; kk++)
                xp[kk] = *(const u64*)&myx[j*10 + 2*kk];
            u64 wx = pkd(wv.x), wy = pkd(wv.y), wz = pkd(wv.z), wq = pkd(wv.w);
            #pragma unroll
            for (int kk = 0; kk < 4; kk++) {
                acc[0][kk] = ffma2(xp[kk], wx, acc[0][kk]);
                acc[1][kk] = ffma2(xp[kk], wy, acc[1][kk]);
                acc[2][kk] = ffma2(xp[kk], wz, acc[2][kk]);
                acc[3][kk] = ffma2(xp[kk], wq, acc[3][kk]);
            }
        }
        float hv[4][8];
        #pragma unroll
        for (int c = 0; c < 4; c++) {
            #pragma unroll
            for (int kk = 0; kk < 4; kk++)
                up2(acc[c][kk], hv[c][2*kk], hv[c][2*kk+1]);
        }
        float part[8];
        #pragma unroll
        for (int k = 0; k < 8; k++) {
            float p = 0.f;
            #pragma unroll
            for (int c = 0; c < 4; c++) {
                float h = fmaxf(hv[c][k], 0.f);
                p = fmaf(h, sw2[lane*4 + c], p);
            }
            part[k] = p;
        }
        #pragma unroll
        for (int off = 16; off > 0; off >>= 1) {
            #pragma unroll
            for (int k = 0; k < 8; k++)
                part[k] += __shfl_xor_sync(0xffffffffu, part[k], off);
        }
        if (lane < 8) {
            int item = base + lane;
            float logit = part[lane] + b2;
            float p = 1.f / (1.f + __expf(-logit));
            float mk = mask[item];
            out[item]          = p * mk;
            out[NITEMS + item] = (float)correct_seq[item] * mk;
        }
        __syncwarp();
    }
}

// ============================================================================
extern "C" void kernel_launch(void* const* d_in, const int* in_sizes, int n_in,
                              void* d_out, int out_size) {
    const int*   skill_seq         = (const int*)  d_in[0];
    const int*   correct_seq       = (const int*)  d_in[1];
    const float* mask              = (const float*)d_in[2];
    const float* skill_embed       = (const float*)d_in[3];
    const float* key_memory        = (const float*)d_in[4];
    const float* value_init        = (const float*)d_in[5];
    const float* interaction_embed = (const float*)d_in[6];
    const float* erase_W           = (const float*)d_in[7];
    const float* erase_b           = (const float*)d_in[8];
    const float* add_W             = (const float*)d_in[9];
    const float* add_b             = (const float*)d_in[10];
    const float* fc1_W             = (const float*)d_in[11];
    const float* fc1_b             = (const float*)d_in[12];
    const float* fc2_W             = (const float*)d_in[13];
    const float* fc2_b             = (const float*)d_in[14];
    float* out = (float*)d_out;

    const int k0_smem = (64*HHX + HHX + 8*256) * sizeof(float);            // ~41.5 KB
    const int k3_smem = (64*HHX + HHX + 8*64*10) * sizeof(float);          // ~53 KB
    cudaFuncSetAttribute(k3_mlp, cudaFuncAttributeMaxDynamicSharedMemorySize, k3_smem);

    k0_tables<<<407, 256, k0_smem>>>(skill_embed, key_memory, interaction_embed,
                                     erase_W, erase_b, add_W, add_b, fc1_W, fc1_b);
    k2_scan<<<BB, 64>>>(value_init, skill_seq, correct_seq);
    k3_mlp<<<444, 256, k3_smem>>>(skill_seq, correct_seq, mask,
                                  fc1_W, fc2_W, fc2_b, out);
}

// round 10
// speedup vs baseline: 2.3830x; 1.0662x over previous
#include <cuda_runtime.h>
#include <cstdint>

#define BB 512
#define TT 200
#define MM 50
#define DKX 64
#define DVX 64
#define HHX 128
#define NSK 1000
#define NITEMS (BB*TT)

typedef unsigned long long u64;
typedef unsigned int u32;

// ---- packed f32x2 helpers ----
__device__ __forceinline__ u64 pk2(float lo, float hi) {
    u64 r; asm("mov.b64 %0,{%1,%2};" : "=l"(r) : "f"(lo), "f"(hi)); return r;
}
__device__ __forceinline__ u64 pkd(float x) {
    u64 r; asm("mov.b64 %0,{%1,%1};" : "=l"(r) : "f"(x)); return r;
}
__device__ __forceinline__ void up2(u64 v, float& lo, float& hi) {
    asm("mov.b64 {%0,%1},%2;" : "=f"(lo), "=f"(hi) : "l"(v));
}
__device__ __forceinline__ u64 ffma2(u64 a, u64 b, u64 c) {
    u64 d; asm("fma.rn.f32x2 %0,%1,%2,%3;" : "=l"(d) : "l"(a), "l"(b), "l"(c)); return d;
}
__device__ __forceinline__ u32 f2tf32(float x) {
    u32 t; asm("cvt.rna.tf32.f32 %0, %1;" : "=r"(t) : "f"(x)); return t;
}

#define MMA_TF32(c0,c1,c2,c3,a0,a1,a2,a3,b0,b1) \
    asm("mma.sync.aligned.m16n8k8.row.col.f32.tf32.tf32.f32 " \
        "{%0,%1,%2,%3},{%4,%5,%6,%7},{%8,%9},{%0,%1,%2,%3};" \
        : "+f"(c0),"+f"(c1),"+f"(c2),"+f"(c3) \
        : "r"(a0),"r"(a1),"r"(a2),"r"(a3),"r"(b0),"r"(b1))

// ---- tables + scratch ----
__device__ float tw[NSK*MM];          // softmax(q_s . K^T) per skill
__device__ float tea[2*NSK*DVX*2];    // interleaved (e,a) per interaction id
__device__ float qW[NSK*HHX];         // skill_embed[s] @ W1_top + b1
__device__ float g_read[NITEMS*DVX];
__device__ u64   g_W1frag[4096];      // W1_low in tf32 B-fragment order [kk][nn][lane]

// ============================================================================
// Kernel 0: build all tables.
//   [0,125)   role A: tw    (8 skills/block)
//   [125,375) role B: tea   (8 vis/block)
//   [375,407) role C: qW    (32 skills/block)
//   407       role D: W1frag (tf32 B-fragment repack of fc1_W rows 64..127)
// ============================================================================
__global__ __launch_bounds__(256) void k0_tables(
    const float* __restrict__ skill_embed,
    const float* __restrict__ key_memory,
    const float* __restrict__ interaction_embed,
    const float* __restrict__ erase_W,
    const float* __restrict__ erase_b,
    const float* __restrict__ add_W,
    const float* __restrict__ add_b,
    const float* __restrict__ fc1_W,
    const float* __restrict__ fc1_b)
{
    extern __shared__ float smem[];
    int tid  = threadIdx.x;
    int w    = tid >> 5;
    int lane = tid & 31;
    int bid  = blockIdx.x;

    if (bid < 125) {
        float* sKt = smem;            // [64][52]
        float* sq  = sKt + DKX*52;    // [8 warps][64]
        for (int idx = tid; idx < MM*DKX; idx += 256) {
            int m = idx / DKX, i = idx % DKX;
            sKt[i*52 + m] = key_memory[m*DKX + i];
        }
        __syncthreads();
        int s = bid*8 + w;
        float* mq = sq + w*64;
        mq[lane]    = skill_embed[s*DKX + lane];
        mq[lane+32] = skill_embed[s*DKX + lane+32];
        __syncwarp();
        const bool v1 = (lane + 32) < MM;
        float d0 = 0.f, d1 = 0.f;
        #pragma unroll 8
        for (int i = 0; i < DKX; i++) {
            float qi = mq[i];
            d0 = fmaf(qi, sKt[i*52 + lane], d0);
            d1 = fmaf(qi, sKt[i*52 + lane + 32], d1);
        }
        float mx = fmaxf(d0, v1 ? d1 : -1e30f);
        #pragma unroll
        for (int off = 16; off > 0; off >>= 1)
            mx = fmaxf(mx, __shfl_xor_sync(0xffffffffu, mx, off));
        float x0 = __expf(d0 - mx);
        float x1 = v1 ? __expf(d1 - mx) : 0.f;
        float sm = x0 + x1;
        #pragma unroll
        for (int off = 16; off > 0; off >>= 1)
            sm += __shfl_xor_sync(0xffffffffu, sm, off);
        float inv = 1.f / sm;
        tw[s*MM + lane] = x0 * inv;
        if (v1) tw[s*MM + lane + 32] = x1 * inv;
    } else if (bid < 375) {
        float* seW = smem;
        float* saW = seW + DKX*DVX;
        float* sv  = saW + DKX*DVX;
        for (int idx = tid; idx < DKX*DVX; idx += 256) {
            seW[idx] = erase_W[idx];
            saW[idx] = add_W[idx];
        }
        __syncthreads();
        int vi = (bid - 125)*8 + w;
        float* mv = sv + w*64;
        mv[lane]    = interaction_embed[vi*DVX + lane];
        mv[lane+32] = interaction_embed[vi*DVX + lane+32];
        __syncwarp();
        float E0 = erase_b[lane], E1 = erase_b[lane+32];
        float A0 = add_b[lane],   A1 = add_b[lane+32];
        #pragma unroll 8
        for (int i = 0; i < DVX; i++) {
            float vv = mv[i];
            E0 = fmaf(vv, seW[i*DVX + lane],    E0);
            E1 = fmaf(vv, seW[i*DVX + lane+32], E1);
            A0 = fmaf(vv, saW[i*DVX + lane],    A0);
            A1 = fmaf(vv, saW[i*DVX + lane+32], A1);
        }
        float2 ea0 = make_float2(1.f/(1.f + __expf(-E0)), tanhf(A0));
        float2 ea1 = make_float2(1.f/(1.f + __expf(-E1)), tanhf(A1));
        *(float2*)&tea[(vi*DVX + lane)*2]      = ea0;
        *(float2*)&tea[(vi*DVX + lane+32)*2]   = ea1;
    } else if (bid < 407) {
        float* sW1t = smem;            // [64][128]
        float* sb1  = sW1t + 64*HHX;
        float* sq   = sb1 + HHX;       // [8 warps][256]
        for (int idx = tid; idx < 64*HHX; idx += 256) sW1t[idx] = fc1_W[idx];
        if (tid < HHX) sb1[tid] = fc1_b[tid];
        __syncthreads();
        int sbase = (bid - 375)*32 + w*4;
        float* mq = sq + w*256;
        #pragma unroll
        for (int k = 0; k < 4; k++) {
            int s = sbase + k; if (s >= NSK) s = NSK-1;
            mq[lane*4 + k]      = skill_embed[s*DKX + lane];
            mq[(lane+32)*4 + k] = skill_embed[s*DKX + lane+32];
        }
        __syncwarp();
        u64 acc2[4][2];
        #pragma unroll
        for (int c = 0; c < 4; c++) {
            u64 bb = pkd(sb1[lane*4 + c]);
            acc2[c][0] = bb; acc2[c][1] = bb;
        }
        #pragma unroll 4
        for (int i = 0; i < DKX; i++) {
            u64 q01 = *(const u64*)&mq[i*4];
            u64 q23 = *(const u64*)&mq[i*4 + 2];
            float4 w4 = *(const float4*)&sW1t[i*HHX + lane*4];
            u64 wx = pkd(w4.x), wy = pkd(w4.y), wz = pkd(w4.z), wq = pkd(w4.w);
            acc2[0][0] = ffma2(q01, wx, acc2[0][0]);
            acc2[0][1] = ffma2(q23, wx, acc2[0][1]);
            acc2[1][0] = ffma2(q01, wy, acc2[1][0]);
            acc2[1][1] = ffma2(q23, wy, acc2[1][1]);
            acc2[2][0] = ffma2(q01, wz, acc2[2][0]);
            acc2[2][1] = ffma2(q23, wz, acc2[2][1]);
            acc2[3][0] = ffma2(q01, wq, acc2[3][0]);
            acc2[3][1] = ffma2(q23, wq, acc2[3][1]);
        }
        float A[4][4];
        #pragma unroll
        for (int c = 0; c < 4; c++) {
            up2(acc2[c][0], A[c][0], A[c][1]);
            up2(acc2[c][1], A[c][2], A[c][3]);
        }
        #pragma unroll
        for (int k = 0; k < 4; k++) {
            int s = sbase + k;
            if (s < NSK) {
                float4 o = make_float4(A[0][k], A[1][k], A[2][k], A[3][k]);
                *(float4*)&qW[s*HHX + lane*4] = o;
            }
        }
    } else {
        // role D: repack fc1_W rows 64..127 into tf32 B fragments.
        // B frag for tile (kk,nn), lane L: b0 = W1low[kk*8 + (L&3)][nn*8 + (L>>2)]
        //                                  b1 = W1low[kk*8 + (L&3)+4][nn*8 + (L>>2)]
        for (int idx = tid; idx < 4096; idx += 256) {
            int kk = idx >> 9;
            int rem = idx & 511;
            int nn = rem >> 5;
            int l5 = rem & 31;
            int klo = kk*8 + (l5 & 3);
            int n   = nn*8 + (l5 >> 2);
            float wlo = fc1_W[(64 + klo)*HHX + n];
            float whi = fc1_W[(64 + klo + 4)*HHX + n];
            u32 t0 = f2tf32(wlo), t1 = f2tf32(whi);
            g_W1frag[idx] = ((u64)t1 << 32) | (u64)t0;
        }
    }
}

// ============================================================================
// Kernel 2: sequential memory scan (round-9, known good).
// ============================================================================
__global__ __launch_bounds__(64) void k2_scan(
    const float* __restrict__ value_init,
    const int*   __restrict__ skill_seq,
    const int*   __restrict__ correct_seq)
{
    __shared__ __align__(16) float sw[TT*52];
    __shared__ int ss[TT];
    __shared__ int svi[TT];
    int b = blockIdx.x;
    int v = threadIdx.x;
    const int base = b * TT;

    for (int i = v; i < TT; i += 64) {
        int s = skill_seq[base + i];
        ss[i]  = s;
        svi[i] = s + correct_seq[base + i]*NSK;
    }
    __syncthreads();

    {
        int wp = v >> 5, lane = v & 31;
        if (lane < 25) {
            for (int t = wp; t < TT; t += 2) {
                u32 dst = (u32)__cvta_generic_to_shared(&sw[t*52 + lane*2]);
                const float* src = &tw[ss[t]*MM + lane*2];
                asm volatile("cp.async.ca.shared.global [%0], [%1], 8;"
                             :: "r"(dst), "l"(src));
            }
        }
        for (int i = v; i < TT; i += 64) { sw[i*52 + 50] = 0.f; sw[i*52 + 51] = 0.f; }
        asm volatile("cp.async.commit_group;");
    }

    u64 mem[25];
    #pragma unroll
    for (int m = 0; m < 25; m++)
        mem[m] = pk2(value_init[(2*m)*DVX + v], value_init[(2*m+1)*DVX + v]);

    float2 eaA = *(const float2*)&tea[(svi[0]*DVX + v)*2];
    float2 eaB = *(const float2*)&tea[(svi[1]*DVX + v)*2];

    asm volatile("cp.async.wait_group 0;" ::: "memory");
    __syncthreads();

    for (int t = 0; t < TT; t++) {
        float e = eaA.x, a = eaA.y;
        eaA = eaB;
        if (t + 2 < TT)
            eaB = *(const float2*)&tea[(svi[t+2]*DVX + v)*2];
        u64 nee = pkd(-e);
        u64 aa  = pkd(a);
        const float* wr = &sw[t*52];
        u64 r[4] = {0ull,0ull,0ull,0ull};
        #pragma unroll
        for (int i = 0; i < 12; i++) {
            float4 w4 = *(const float4*)&wr[4*i];
            u64 wlo = pk2(w4.x, w4.y);
            u64 whi = pk2(w4.z, w4.w);
            int m = 2*i;
            r[m & 3]     = ffma2(wlo, mem[m],   r[m & 3]);
            u64 t1       = ffma2(mem[m],   nee, aa);
            mem[m]       = ffma2(wlo, t1,  mem[m]);
            r[(m+1) & 3] = ffma2(whi, mem[m+1], r[(m+1) & 3]);
            u64 t2       = ffma2(mem[m+1], nee, aa);
            mem[m+1]     = ffma2(whi, t2,  mem[m+1]);
        }
        {
            u64 ww = *(const u64*)&wr[48];
            r[0]    = ffma2(ww, mem[24], r[0]);
            u64 t1  = ffma2(mem[24], nee, aa);
            mem[24] = ffma2(ww, t1, mem[24]);
        }
        float x0, x1, y0, y1, z0, z1, u0, u1;
        up2(r[0], x0, x1); up2(r[1], y0, y1);
        up2(r[2], z0, z1); up2(r[3], u0, u1);
        g_read[(base + t)*DVX + v] = ((x0+x1) + (y0+y1)) + ((z0+z1) + (u0+u1));
    }
}

// ============================================================================
// Kernel 3: MLP via tf32 tensor cores. 256 thr (8 warps), warp = 16 items,
// full N=128.  C[m16 x n8] frags seeded from fp32 qW[s]; K=64 in 8 k-steps;
// epilogue relu + w2 dot + quad shuffle reduce.
//   A frag (x):  a0=(r,c) a1=(r+8,c) a2=(r,c+4) a3=(r+8,c+4), r=lane>>2,c=lane&3
//   B frag (W1): prepacked by k0 role D (conflict-free LDS.64)
//   C frag:      c0=(r,2c) c1=(r,2c+1) c2=(r+8,2c) c3=(r+8,2c+1)
// ============================================================================
#define XSTR 68   // xs row stride (floats): conflict-free A-frag loads

__global__ __launch_bounds__(256,2) void k3_mma(
    const int*   __restrict__ skill_seq,
    const int*   __restrict__ correct_seq,
    const float* __restrict__ mask,
    const float* __restrict__ fc2_W,
    const float* __restrict__ fc2_b,
    float*       __restrict__ out)
{
    extern __shared__ float smem[];
    u64*   sW1f = (u64*)smem;            // [4096] = 32 KB
    float* sw2  = smem + 8192;           // [128]
    float* xs   = sw2 + HHX;             // [8 warps][16*XSTR]

    int tid  = threadIdx.x;
    int wp   = tid >> 5;
    int lane = tid & 31;

    for (int idx = tid; idx < 4096; idx += 256) sW1f[idx] = g_W1frag[idx];
    if (tid < HHX) sw2[tid] = fc2_W[tid];
    __syncthreads();
    float b2 = fc2_b[0];

    const int base = blockIdx.x*128 + wp*16;    // this warp's 16 items
    float* myxs = xs + wp * (16*XSTR);

    // ---- stage x (tf32 bit patterns) into xs[m][k], row stride XSTR ----
    #pragma unroll
    for (int m = 0; m < 16; m++) {
        float2 xv = *(const float2*)&g_read[(base + m)*DVX + 2*lane];
        u32 t0 = f2tf32(xv.x), t1 = f2tf32(xv.y);
        *(u64*)&myxs[m*XSTR + 2*lane] = ((u64)t1 << 32) | (u64)t0;
    }

    // ---- C init from qW (fp32 seed) ----
    int r = lane >> 2, c = lane & 3;
    int itemA = base + r, itemB = base + r + 8;
    int sA = skill_seq[itemA], sB = skill_seq[itemB];
    float cf[16][4];
    #pragma unroll
    for (int nn = 0; nn < 16; nn++) {
        float2 qa = *(const float2*)&qW[sA*HHX + nn*8 + 2*c];
        float2 qb = *(const float2*)&qW[sB*HHX + nn*8 + 2*c];
        cf[nn][0] = qa.x; cf[nn][1] = qa.y;
        cf[nn][2] = qb.x; cf[nn][3] = qb.y;
    }
    __syncwarp();

    // ---- mma mainloop: 8 k-steps x 16 n-tiles ----
    #pragma unroll
    for (int kk = 0; kk < 8; kk++) {
        u32 a0 = __float_as_uint(myxs[ r     *XSTR + kk*8 + c    ]);
        u32 a1 = __float_as_uint(myxs[(r+8)  *XSTR + kk*8 + c    ]);
        u32 a2 = __float_as_uint(myxs[ r     *XSTR + kk*8 + c + 4]);
        u32 a3 = __float_as_uint(myxs[(r+8)  *XSTR + kk*8 + c + 4]);
        #pragma unroll
        for (int nn = 0; nn < 16; nn++) {
            u64 bb = sW1f[(kk*16 + nn)*32 + lane];
            u32 b0 = (u32)bb, b1 = (u32)(bb >> 32);
            MMA_TF32(cf[nn][0], cf[nn][1], cf[nn][2], cf[nn][3],
                     a0, a1, a2, a3, b0, b1);
        }
    }

    // ---- epilogue: relu + w2 dot, quad reduce over c ----
    float pA = 0.f, pB = 0.f;
    #pragma unroll
    for (int nn = 0; nn < 16; nn++) {
        float2 w2v = *(const float2*)&sw2[nn*8 + 2*c];
        pA = fmaf(fmaxf(cf[nn][0], 0.f), w2v.x, pA);
        pA = fmaf(fmaxf(cf[nn][1], 0.f), w2v.y, pA);
        pB = fmaf(fmaxf(cf[nn][2], 0.f), w2v.x, pB);
        pB = fmaf(fmaxf(cf[nn][3], 0.f), w2v.y, pB);
    }
    pA += __shfl_xor_sync(0xffffffffu, pA, 1);
    pA += __shfl_xor_sync(0xffffffffu, pA, 2);
    pB += __shfl_xor_sync(0xffffffffu, pB, 1);
    pB += __shfl_xor_sync(0xffffffffu, pB, 2);

    if (c == 0) {
        float mkA = mask[itemA];
        float pa  = 1.f / (1.f + __expf(-(pA + b2)));
        out[itemA]          = pa * mkA;
        out[NITEMS + itemA] = (float)correct_seq[itemA] * mkA;
        float mkB = mask[itemB];
        float pb  = 1.f / (1.f + __expf(-(pB + b2)));
        out[itemB]          = pb * mkB;
        out[NITEMS + itemB] = (float)correct_seq[itemB] * mkB;
    }
}

// ============================================================================
extern "C" void kernel_launch(void* const* d_in, const int* in_sizes, int n_in,
                              void* d_out, int out_size) {
    const int*   skill_seq         = (const int*)  d_in[0];
    const int*   correct_seq       = (const int*)  d_in[1];
    const float* mask              = (const float*)d_in[2];
    const float* skill_embed       = (const float*)d_in[3];
    const float* key_memory        = (const float*)d_in[4];
    const float* value_init        = (const float*)d_in[5];
    const float* interaction_embed = (const float*)d_in[6];
    const float* erase_W           = (const float*)d_in[7];
    const float* erase_b           = (const float*)d_in[8];
    const float* add_W             = (const float*)d_in[9];
    const float* add_b             = (const float*)d_in[10];
    const float* fc1_W             = (const float*)d_in[11];
    const float* fc1_b             = (const float*)d_in[12];
    const float* fc2_W             = (const float*)d_in[13];
    const float* fc2_b             = (const float*)d_in[14];
    float* out = (float*)d_out;

    const int k0_smem = (64*HHX + HHX + 8*256) * sizeof(float);               // ~41.5 KB
    const int k3_smem = 4096*8 + (HHX + 8*16*XSTR) * (int)sizeof(float);      // ~68 KB
    cudaFuncSetAttribute(k3_mma, cudaFuncAttributeMaxDynamicSharedMemorySize, k3_smem);

    k0_tables<<<408, 256, k0_smem>>>(skill_embed, key_memory, interaction_embed,
                                     erase_W, erase_b, add_W, add_b, fc1_W, fc1_b);
    k2_scan<<<BB, 64>>>(value_init, skill_seq, correct_seq);
    k3_mma<<<NITEMS/128, 256, k3_smem>>>(skill_seq, correct_seq, mask,
                                         fc2_W, fc2_b, out);
}